// round 1
// baseline (speedup 1.0000x reference)
#include <cuda_runtime.h>
#include <cstdint>
#include <cstddef>

#define CH   40
#define TT   2000
#define LL   256
#define NB   64
#define NEGF (-1.0e30f)
#define LOG2E 1.4426950408889634f
#define LN2   0.6931471805599453f

// ---------------- device scratch (no allocations allowed) ----------------
__device__ unsigned long long g_maskkeys[NB * 256];   // rolled unique column keys (40-bit)
__device__ int   g_labels[NB * 256];                  // CTC labels per batch
__device__ int   g_tlen[NB];                          // label counts
__device__ float g_em[(size_t)NB * TT * 256];         // emissions, [n][t][j], scaled by log2(e)
__device__ float g_loss[NB];

// ---------------- small PTX helpers ----------------
__device__ __forceinline__ float ex2f(float x) {
    float r; asm("ex2.approx.ftz.f32 %0, %1;" : "=f"(r) : "f"(x)); return r;
}
__device__ __forceinline__ float lg2f(float x) {
    float r; asm("lg2.approx.ftz.f32 %0, %1;" : "=f"(r) : "f"(x)); return r;
}
__device__ __forceinline__ unsigned long long pk2(float x, float y) {
    unsigned long long r;
    asm("mov.b64 %0, {%1, %2};" : "=l"(r) : "f"(x), "f"(y));
    return r;
}
__device__ __forceinline__ void ffma2(unsigned long long &a, unsigned long long m, unsigned long long d) {
    asm("fma.rn.f32x2 %0, %1, %2, %3;" : "=l"(a) : "l"(m), "l"(d), "l"(a));
}
__device__ __forceinline__ void up2(unsigned long long v, float &x, float &y) {
    asm("mov.b64 {%0, %1}, %2;" : "=f"(x), "=f"(y) : "l"(v));
}

// =====================================================================
// Kernel 1: preprocessing — replicate np.unique(axis=1) + roll + groupby
// One block per batch item, 256 threads (one per target column).
// =====================================================================
__global__ void k_preprocess(const int* __restrict__ targets) {
    const int n = blockIdx.x;
    const int l = threadIdx.x;

    __shared__ unsigned long long skey[256];
    __shared__ int sscan[256];
    __shared__ int sinv[256];

    // pack column l into a 40-bit key; channel 0 = most significant bit
    unsigned long long key = 0ull;
#pragma unroll
    for (int c = 0; c < CH; c++) {
        key |= ((unsigned long long)(targets[(n * CH + c) * LL + l] & 1)) << (CH - 1 - c);
    }
    skey[l] = (key << 8) | (unsigned long long)l;   // tie-break by original index
    __syncthreads();

    // bitonic sort, ascending
    for (int k = 2; k <= 256; k <<= 1) {
        for (int j = k >> 1; j > 0; j >>= 1) {
            int ixj = l ^ j;
            if (ixj > l) {
                unsigned long long a = skey[l], b = skey[ixj];
                bool up = ((l & k) == 0);
                if ((a > b) == up) { skey[l] = b; skey[ixj] = a; }
            }
            __syncthreads();
        }
    }

    // unique heads + inclusive scan -> unique ids
    unsigned long long kv = skey[l] >> 8;
    unsigned long long kvp = (l > 0) ? (skey[l - 1] >> 8) : 0ull;
    int head = (l == 0 || kv != kvp) ? 1 : 0;
    sscan[l] = head;
    __syncthreads();
    for (int off = 1; off < 256; off <<= 1) {
        int v = sscan[l];
        int w = (l >= off) ? sscan[l - off] : 0;
        __syncthreads();
        sscan[l] = v + w;
        __syncthreads();
    }
    const int u   = sscan[255];
    const int uid = sscan[l] - 1;
    const int orig = (int)(skey[l] & 255ull);
    int inv2 = uid + 1; if (inv2 == u) inv2 = 0;    // (inv+1) % u
    sinv[orig] = inv2;
    if (head) {
        // rolled unique: char index inv2 gets the key of sorted-unique uid
        g_maskkeys[n * 256 + inv2] = kv;
    }
    __syncthreads();   // sinv visible; also all reads of sscan done before reuse

    // labels = run-heads of inv2 sequence, dropping the first run
    int flag = (l > 0 && sinv[l] != sinv[l - 1]) ? 1 : 0;
    int myinv = sinv[l];
    sscan[l] = flag;
    __syncthreads();
    for (int off = 1; off < 256; off <<= 1) {
        int v = sscan[l];
        int w = (l >= off) ? sscan[l - off] : 0;
        __syncthreads();
        sscan[l] = v + w;
        __syncthreads();
    }
    if (flag) g_labels[n * 256 + (sscan[l] - 1)] = myinv;
    if (l == 0) g_tlen[n] = sscan[255];
}

// =====================================================================
// Kernel 2: emission table  em[n][t][j] (scaled by log2 e)
//   j = 0: blank = lp1[n,0,t]
//   j >= 1: sum_c [(1-b)lp0 + b*lp1],  b = bit c of rolled key j
// grid (16, 64), 128 threads; each thread owns one t, packed f32x2 over j.
// =====================================================================
__global__ void __launch_bounds__(128) k_emission(const float* __restrict__ lp) {
    const int n = blockIdx.y;
    const int t = blockIdx.x * 128 + threadIdx.x;

    __shared__ float maskf[CH * 256];   // [c][j] as float 0/1
    for (int idx = threadIdx.x; idx < CH * 256; idx += 128) {
        int c = idx >> 8, j = idx & 255;
        unsigned long long mk = g_maskkeys[n * 256 + j];
        maskf[idx] = (float)((mk >> (CH - 1 - c)) & 1ull);
    }
    __syncthreads();
    if (t >= TT) return;

    const float* lp0 = lp + ((size_t)n * 2 + 0) * CH * TT;
    const float* lp1 = lp + ((size_t)n * 2 + 1) * CH * TT;

    unsigned long long d2[CH];
    float base = 0.0f;
    float blank = 0.0f;
#pragma unroll
    for (int c = 0; c < CH; c++) {
        float x0 = __ldg(lp0 + c * TT + t);
        float x1 = __ldg(lp1 + c * TT + t);
        if (c == 0) blank = x1;
        float dd = x1 - x0;
        base += x0;
        d2[c] = pk2(dd, dd);
    }

    float* out = g_em + ((size_t)n * TT + t) * 256;
    out[0] = blank * LOG2E;

    const unsigned long long b2 = pk2(base, base);
    for (int j8 = 0; j8 < 32; j8++) {
        unsigned long long acc0 = b2, acc1 = b2, acc2 = b2, acc3 = b2;
#pragma unroll
        for (int c = 0; c < CH; c++) {
            const float4* mp = (const float4*)(maskf + c * 256 + j8 * 8);
            float4 f0 = mp[0];
            float4 f1 = mp[1];
            ffma2(acc0, pk2(f0.x, f0.y), d2[c]);
            ffma2(acc1, pk2(f0.z, f0.w), d2[c]);
            ffma2(acc2, pk2(f1.x, f1.y), d2[c]);
            ffma2(acc3, pk2(f1.z, f1.w), d2[c]);
        }
        float vx, vy;
        int j = j8 * 8;
        up2(acc0, vx, vy);
        if (j > 0) out[j] = vx * LOG2E;
        out[j + 1] = vy * LOG2E;
        up2(acc1, vx, vy);
        out[j + 2] = vx * LOG2E; out[j + 3] = vy * LOG2E;
        up2(acc2, vx, vy);
        out[j + 4] = vx * LOG2E; out[j + 5] = vy * LOG2E;
        up2(acc3, vx, vy);
        out[j + 6] = vx * LOG2E; out[j + 7] = vy * LOG2E;
    }
}

// =====================================================================
// Kernel 3: CTC forward in base-2 log domain. 64 blocks x 512 threads,
// one state per thread, ping-pong alpha in shared, 1 barrier/step,
// depth-8 register prefetch of the emission column.
// =====================================================================
#define CTC_STEP()                                                        \
    do {                                                                  \
        float a  = A[cur][p + 2];                                         \
        float a1 = A[cur][p + 1];                                         \
        float a2 = A[cur][p];                                             \
        a2 = skip ? a2 : NEG2;                                            \
        float hi = fmaxf(a, a1), lo = fminf(a, a1);                       \
        float m  = fmaxf(hi, a2);                                         \
        float sec = fminf(hi, fmaxf(lo, a2));                             \
        float th  = fminf(lo, a2);                                        \
        float s = 1.0f + ex2f(sec - m) + ex2f(th - m);                    \
        A[cur ^ 1][p + 2] = m + lg2f(s) + e;                              \
        __syncthreads();                                                  \
        cur ^= 1;                                                         \
    } while (0)

__global__ void __launch_bounds__(512) k_ctc() {
    const int n = blockIdx.x;
    const int p = threadIdx.x;
    __shared__ float A[2][516];

    const float NEG2 = NEGF * LOG2E;
    const int tlen = g_tlen[n];

    int lab = 0;
    bool skip = false;
    if (p & 1) {
        int k = (p - 1) >> 1;
        if (k < tlen) {
            lab = g_labels[n * 256 + k];
            if (k >= 1) {
                int labm2 = g_labels[n * 256 + k - 1];
                skip = (lab != 0) && (lab != labm2);
            }
        }
    }

    const float* emn = g_em + (size_t)n * TT * 256;
    const float* labcol = emn + lab;

    if (p < 2) {
        A[0][p] = NEG2; A[1][p] = NEG2;          // sentinels
        A[0][p + 2] = __ldg(labcol);             // t = 0 emission
    } else {
        A[0][p + 2] = NEG2;
    }

    float pre[8];
#pragma unroll
    for (int k = 0; k < 8; k++) pre[k] = __ldg(labcol + (size_t)(1 + k) * 256);
    __syncthreads();

    int cur = 0;
    int t = 1;
    for (int chunk = 0; chunk < 249; chunk++) {
#pragma unroll
        for (int k = 0; k < 8; k++) {
            float e = pre[k];
            if (t + 8 < TT) pre[k] = __ldg(labcol + (size_t)(t + 8) * 256);
            CTC_STEP();
            t++;
        }
    }
#pragma unroll
    for (int k = 0; k < 7; k++) {
        float e = pre[k];
        CTC_STEP();
        t++;
    }

    // t == 2000; final alpha lives in A[cur]
    if (p == 0) {
        float ea = A[cur][2 * tlen + 2];
        float eb = A[cur][2 * tlen + 1];
        float m = fmaxf(ea, eb);
        float l2 = m + lg2f(ex2f(ea - m) + ex2f(eb - m));
        g_loss[n] = -l2 * LN2;
    }
}

// =====================================================================
// Kernel 4: deterministic mean
// =====================================================================
__global__ void k_reduce(float* __restrict__ out) {
    if (threadIdx.x == 0) {
        float s = 0.0f;
        for (int i = 0; i < NB; i++) s += g_loss[i];
        out[0] = s * (1.0f / (float)NB);
    }
}

// =====================================================================
extern "C" void kernel_launch(void* const* d_in, const int* in_sizes, int n_in,
                              void* d_out, int out_size) {
    const float* lp = (const float*)d_in[0];
    const int*   tg = (const int*)d_in[1];
    // defensive: identify inputs by size (log_probs = 10,240,000; targets = 655,360)
    if (n_in >= 2 && in_sizes[0] == NB * CH * LL) {
        lp = (const float*)d_in[1];
        tg = (const int*)d_in[0];
    }

    k_preprocess<<<NB, 256>>>(tg);
    dim3 g2((TT + 127) / 128, NB);
    k_emission<<<g2, 128>>>(lp);
    k_ctc<<<NB, 512>>>();
    k_reduce<<<1, 32>>>((float*)d_out);
}

// round 3
// speedup vs baseline: 1.1075x; 1.1075x over previous
#include <cuda_runtime.h>
#include <cuda_fp16.h>
#include <cstdint>
#include <cstddef>

#define CH   40
#define TT   2000
#define LL   256
#define NB   64
#define NEGF (-1.0e30f)
#define LOG2E 1.4426950408889634f
#define LN2   0.6931471805599453f

// ---------------- device scratch ----------------
__device__ unsigned long long g_maskkeys[NB * 256];   // rolled unique column keys (40-bit)
__device__ int   g_labels[NB * 256];
__device__ int   g_tlen[NB];
__device__ float g_em[(size_t)NB * TT * 256];         // emissions, [n][t][j], log2-scaled
__device__ float g_loss[NB];

// ---------------- PTX helpers ----------------
__device__ __forceinline__ float ex2f(float x) {
    float r; asm("ex2.approx.ftz.f32 %0, %1;" : "=f"(r) : "f"(x)); return r;
}
__device__ __forceinline__ float lg2f(float x) {
    float r; asm("lg2.approx.ftz.f32 %0, %1;" : "=f"(r) : "f"(x)); return r;
}
__device__ __forceinline__ unsigned long long pk2(float x, float y) {
    unsigned long long r;
    asm("mov.b64 %0, {%1, %2};" : "=l"(r) : "f"(x), "f"(y));
    return r;
}
__device__ __forceinline__ void ffma2(unsigned long long &a, unsigned long long m, unsigned long long d) {
    asm("fma.rn.f32x2 %0, %1, %2, %3;" : "=l"(a) : "l"(m), "l"(d), "l"(a));
}
__device__ __forceinline__ void up2(unsigned long long v, float &x, float &y) {
    asm("mov.b64 {%0, %1}, %2;" : "=f"(x), "=f"(y) : "l"(v));
}

// =====================================================================
// Kernel 1: preprocessing (verbatim from round-1; verified rel_err 0.0)
// =====================================================================
__global__ void k_preprocess(const int* __restrict__ targets) {
    const int n = blockIdx.x;
    const int l = threadIdx.x;

    __shared__ unsigned long long skey[256];
    __shared__ int sscan[256];
    __shared__ int sinv[256];

    unsigned long long key = 0ull;
#pragma unroll
    for (int c = 0; c < CH; c++) {
        key |= ((unsigned long long)(targets[(n * CH + c) * LL + l] & 1)) << (CH - 1 - c);
    }
    skey[l] = (key << 8) | (unsigned long long)l;
    __syncthreads();

    for (int k = 2; k <= 256; k <<= 1) {
        for (int j = k >> 1; j > 0; j >>= 1) {
            int ixj = l ^ j;
            if (ixj > l) {
                unsigned long long a = skey[l], b = skey[ixj];
                bool up = ((l & k) == 0);
                if ((a > b) == up) { skey[l] = b; skey[ixj] = a; }
            }
            __syncthreads();
        }
    }

    unsigned long long kv = skey[l] >> 8;
    unsigned long long kvp = (l > 0) ? (skey[l - 1] >> 8) : 0ull;
    int head = (l == 0 || kv != kvp) ? 1 : 0;
    sscan[l] = head;
    __syncthreads();
    for (int off = 1; off < 256; off <<= 1) {
        int v = sscan[l];
        int w = (l >= off) ? sscan[l - off] : 0;
        __syncthreads();
        sscan[l] = v + w;
        __syncthreads();
    }
    const int u   = sscan[255];
    const int uid = sscan[l] - 1;
    const int orig = (int)(skey[l] & 255ull);
    int inv2 = uid + 1; if (inv2 == u) inv2 = 0;
    sinv[orig] = inv2;
    if (head) g_maskkeys[n * 256 + inv2] = kv;
    __syncthreads();

    int flag = (l > 0 && sinv[l] != sinv[l - 1]) ? 1 : 0;
    int myinv = sinv[l];
    sscan[l] = flag;
    __syncthreads();
    for (int off = 1; off < 256; off <<= 1) {
        int v = sscan[l];
        int w = (l >= off) ? sscan[l - off] : 0;
        __syncthreads();
        sscan[l] = v + w;
        __syncthreads();
    }
    if (flag) g_labels[n * 256 + (sscan[l] - 1)] = myinv;
    if (l == 0) g_tlen[n] = sscan[255];
}

// =====================================================================
// Kernel 2: emission table (verbatim from round-1; verified rel_err 0.0)
// =====================================================================
__global__ void __launch_bounds__(128) k_emission(const float* __restrict__ lp) {
    const int n = blockIdx.y;
    const int t = blockIdx.x * 128 + threadIdx.x;

    __shared__ float maskf[CH * 256];
    for (int idx = threadIdx.x; idx < CH * 256; idx += 128) {
        int c = idx >> 8, j = idx & 255;
        unsigned long long mk = g_maskkeys[n * 256 + j];
        maskf[idx] = (float)((mk >> (CH - 1 - c)) & 1ull);
    }
    __syncthreads();
    if (t >= TT) return;

    const float* lp0 = lp + ((size_t)n * 2 + 0) * CH * TT;
    const float* lp1 = lp + ((size_t)n * 2 + 1) * CH * TT;

    unsigned long long d2[CH];
    float base = 0.0f;
    float blank = 0.0f;
#pragma unroll
    for (int c = 0; c < CH; c++) {
        float x0 = __ldg(lp0 + c * TT + t);
        float x1 = __ldg(lp1 + c * TT + t);
        if (c == 0) blank = x1;
        float dd = x1 - x0;
        base += x0;
        d2[c] = pk2(dd, dd);
    }

    float* out = g_em + ((size_t)n * TT + t) * 256;
    out[0] = blank * LOG2E;

    const unsigned long long b2 = pk2(base, base);
    for (int j8 = 0; j8 < 32; j8++) {
        unsigned long long acc0 = b2, acc1 = b2, acc2 = b2, acc3 = b2;
#pragma unroll
        for (int c = 0; c < CH; c++) {
            const float4* mp = (const float4*)(maskf + c * 256 + j8 * 8);
            float4 f0 = mp[0];
            float4 f1 = mp[1];
            ffma2(acc0, pk2(f0.x, f0.y), d2[c]);
            ffma2(acc1, pk2(f0.z, f0.w), d2[c]);
            ffma2(acc2, pk2(f1.x, f1.y), d2[c]);
            ffma2(acc3, pk2(f1.z, f1.w), d2[c]);
        }
        float vx, vy;
        int j = j8 * 8;
        up2(acc0, vx, vy);
        if (j > 0) out[j] = vx * LOG2E;
        out[j + 1] = vy * LOG2E;
        up2(acc1, vx, vy);
        out[j + 2] = vx * LOG2E; out[j + 3] = vy * LOG2E;
        up2(acc2, vx, vy);
        out[j + 4] = vx * LOG2E; out[j + 5] = vy * LOG2E;
        up2(acc3, vx, vy);
        out[j + 6] = vx * LOG2E; out[j + 7] = vy * LOG2E;
    }
}

// =====================================================================
// Kernel 3: CTC forward, log2 domain. 256 threads / block, 2 states per
// thread (even = 2-term LSE, odd = 3-term). Emission rows staged into a
// 16-slot shared ring via cp.async (prefetch distance 8, 2 warps).
// f16x2 ex2 for the bounded LSE correction terms.
// =====================================================================
__global__ void __launch_bounds__(256) k_ctc() {
    const int n = blockIdx.x;
    const int tid = threadIdx.x;      // 0..255
    const int k = tid;                // handles states 2k (even), 2k+1 (odd)

    __shared__ __align__(16) float A[2][520];      // state p at idx p+2
    __shared__ __align__(16) float sEm[16][256];   // emission row ring

    const int tlen = g_tlen[n];
    const float* emn = g_em + (size_t)n * TT * 256;

    for (int i = tid; i < 520; i += 256) { A[0][i] = NEGF; A[1][i] = NEGF; }

    // per-thread label / skip for the odd state
    int labO = 0; bool skip = false;
    if (k < tlen) {
        labO = g_labels[n * 256 + k];
        if (k >= 1) {
            int lm2 = g_labels[n * 256 + k - 1];
            skip = (labO != 0) && (labO != lm2);
        }
    }

    // preload emission rows 1..8 into ring (64 threads x 16B = 1KB/row)
    if (tid < 64) {
        for (int r = 1; r <= 8; ++r) {
            uint32_t dst = (uint32_t)__cvta_generic_to_shared(&sEm[r & 15][tid * 4]);
            const float* src = emn + (size_t)r * 256 + tid * 4;
            asm volatile("cp.async.cg.shared.global [%0], [%1], 16;\n" :: "r"(dst), "l"(src));
            asm volatile("cp.async.commit_group;\n");
        }
        asm volatile("cp.async.wait_group 7;\n");   // row 1 complete
    }

    if (tid == 0) {
        A[0][2] = __ldg(emn + 0);        // alpha0(state 0) = em0[blank]
        A[0][3] = __ldg(emn + labO);     // alpha0(state 1) = em0[label 0]
    }
    __syncthreads();

    int cur = 0;
#pragma unroll 4
    for (int t = 1; t < TT; ++t) {
        const float* srow = &sEm[t & 15][0];
        float2 a01 = *(const float2*)&A[cur][2 * k + 2];   // alpha(2k), alpha(2k+1)
        float  am1 = A[cur][2 * k + 1];                    // alpha(2k-1)
        float emE = srow[0];
        float emO = srow[labO];

        // even state 2k: lse(alpha(2k), alpha(2k-1))
        float mE   = fmaxf(a01.x, am1);
        float argE = fminf(a01.x, am1) - mE;

        // odd state 2k+1: lse(alpha(2k+1), alpha(2k), skip ? alpha(2k-1))
        float a2v = skip ? am1 : NEGF;
        float hi = fmaxf(a01.y, a01.x);
        float lo = fminf(a01.y, a01.x);
        float mO  = fmaxf(hi, a2v);
        float sec = fminf(hi, fmaxf(lo, a2v));
        float th  = fminf(lo, a2v);

        __half2 e0 = h2exp2(__floats2half2_rn(argE, sec - mO));
        __half2 e1 = h2exp2(__floats2half2_rn(th - mO, th - mO));
        float exE = __low2float(e0);
        float exS = __high2float(e0);
        float exT = __low2float(e1);

        float rE = mE + lg2f(1.0f + exE) + emE;
        float rO = mO + lg2f(1.0f + exS + exT) + emO;

        *(float2*)&A[cur ^ 1][2 * k + 2] = make_float2(rE, rO);

        // stage row t+8
        if (tid < 64) {
            int r = t + 8;
            if (r < TT) {
                uint32_t dst = (uint32_t)__cvta_generic_to_shared(&sEm[r & 15][tid * 4]);
                const float* src = emn + (size_t)r * 256 + tid * 4;
                asm volatile("cp.async.cg.shared.global [%0], [%1], 16;\n" :: "r"(dst), "l"(src));
            }
            asm volatile("cp.async.commit_group;\n");
            asm volatile("cp.async.wait_group 7;\n");   // row t+1 complete
        }
        __syncthreads();
        cur ^= 1;
    }

    if (tid == 0) {
        float ea = A[cur][2 * tlen + 2];
        float eb = A[cur][2 * tlen + 1];
        float m = fmaxf(ea, eb);
        float l2 = m + lg2f(ex2f(ea - m) + ex2f(eb - m));
        g_loss[n] = -l2 * LN2;
    }
}

// =====================================================================
// Kernel 4: deterministic mean
// =====================================================================
__global__ void k_reduce(float* __restrict__ out) {
    if (threadIdx.x == 0) {
        float s = 0.0f;
        for (int i = 0; i < NB; i++) s += g_loss[i];
        out[0] = s * (1.0f / (float)NB);
    }
}

// =====================================================================
extern "C" void kernel_launch(void* const* d_in, const int* in_sizes, int n_in,
                              void* d_out, int out_size) {
    const float* lp = (const float*)d_in[0];
    const int*   tg = (const int*)d_in[1];
    if (n_in >= 2 && in_sizes[0] == NB * CH * LL) {
        lp = (const float*)d_in[1];
        tg = (const int*)d_in[0];
    }

    k_preprocess<<<NB, 256>>>(tg);
    dim3 g2((TT + 127) / 128, NB);
    k_emission<<<g2, 128>>>(lp);
    k_ctc<<<NB, 256>>>();
    k_reduce<<<1, 32>>>((float*)d_out);
}

// round 4
// speedup vs baseline: 1.3789x; 1.2451x over previous
#include <cuda_runtime.h>
#include <cstdint>
#include <cstddef>

#define CH   40
#define TT   2000
#define LL   256
#define NB   64
#define NEGF (-1.0e30f)
#define LOG2E 1.4426950408889634f
#define LN2   0.6931471805599453f

// ---------------- device scratch ----------------
__device__ unsigned long long g_maskkeys[NB * 256];
__device__ int   g_labels[NB * 256];
__device__ int   g_tlen[NB];
__device__ float g_em[(size_t)NB * TT * 256];   // emissions [n][t][j], log2-scaled
__device__ float g_loss[NB];

// ---------------- PTX helpers ----------------
__device__ __forceinline__ float ex2f(float x) {
    float r; asm("ex2.approx.ftz.f32 %0, %1;" : "=f"(r) : "f"(x)); return r;
}
__device__ __forceinline__ float lg2f(float x) {
    float r; asm("lg2.approx.ftz.f32 %0, %1;" : "=f"(r) : "f"(x)); return r;
}
__device__ __forceinline__ unsigned long long pk2(float x, float y) {
    unsigned long long r;
    asm("mov.b64 %0, {%1, %2};" : "=l"(r) : "f"(x), "f"(y));
    return r;
}
__device__ __forceinline__ void ffma2(unsigned long long &a, unsigned long long m, unsigned long long d) {
    asm("fma.rn.f32x2 %0, %1, %2, %3;" : "=l"(a) : "l"(m), "l"(d), "l"(a));
}
__device__ __forceinline__ void up2(unsigned long long v, float &x, float &y) {
    asm("mov.b64 {%0, %1}, %2;" : "=f"(x), "=f"(y) : "l"(v));
}

// =====================================================================
// Kernel 1: preprocessing (verified exact)
// =====================================================================
__global__ void k_preprocess(const int* __restrict__ targets) {
    const int n = blockIdx.x;
    const int l = threadIdx.x;

    __shared__ unsigned long long skey[256];
    __shared__ int sscan[256];
    __shared__ int sinv[256];

    unsigned long long key = 0ull;
#pragma unroll
    for (int c = 0; c < CH; c++) {
        key |= ((unsigned long long)(targets[(n * CH + c) * LL + l] & 1)) << (CH - 1 - c);
    }
    skey[l] = (key << 8) | (unsigned long long)l;
    __syncthreads();

    for (int k = 2; k <= 256; k <<= 1) {
        for (int j = k >> 1; j > 0; j >>= 1) {
            int ixj = l ^ j;
            if (ixj > l) {
                unsigned long long a = skey[l], b = skey[ixj];
                bool up = ((l & k) == 0);
                if ((a > b) == up) { skey[l] = b; skey[ixj] = a; }
            }
            __syncthreads();
        }
    }

    unsigned long long kv = skey[l] >> 8;
    unsigned long long kvp = (l > 0) ? (skey[l - 1] >> 8) : 0ull;
    int head = (l == 0 || kv != kvp) ? 1 : 0;
    sscan[l] = head;
    __syncthreads();
    for (int off = 1; off < 256; off <<= 1) {
        int v = sscan[l];
        int w = (l >= off) ? sscan[l - off] : 0;
        __syncthreads();
        sscan[l] = v + w;
        __syncthreads();
    }
    const int u   = sscan[255];
    const int uid = sscan[l] - 1;
    const int orig = (int)(skey[l] & 255ull);
    int inv2 = uid + 1; if (inv2 == u) inv2 = 0;
    sinv[orig] = inv2;
    if (head) g_maskkeys[n * 256 + inv2] = kv;
    __syncthreads();

    int flag = (l > 0 && sinv[l] != sinv[l - 1]) ? 1 : 0;
    int myinv = sinv[l];
    sscan[l] = flag;
    __syncthreads();
    for (int off = 1; off < 256; off <<= 1) {
        int v = sscan[l];
        int w = (l >= off) ? sscan[l - off] : 0;
        __syncthreads();
        sscan[l] = v + w;
        __syncthreads();
    }
    if (flag) g_labels[n * 256 + (sscan[l] - 1)] = myinv;
    if (l == 0) g_tlen[n] = sscan[255];
}

// =====================================================================
// Kernel 2: emission table (verified exact)
// =====================================================================
__global__ void __launch_bounds__(128) k_emission(const float* __restrict__ lp) {
    const int n = blockIdx.y;
    const int t = blockIdx.x * 128 + threadIdx.x;

    __shared__ float maskf[CH * 256];
    for (int idx = threadIdx.x; idx < CH * 256; idx += 128) {
        int c = idx >> 8, j = idx & 255;
        unsigned long long mk = g_maskkeys[n * 256 + j];
        maskf[idx] = (float)((mk >> (CH - 1 - c)) & 1ull);
    }
    __syncthreads();
    if (t >= TT) return;

    const float* lp0 = lp + ((size_t)n * 2 + 0) * CH * TT;
    const float* lp1 = lp + ((size_t)n * 2 + 1) * CH * TT;

    unsigned long long d2[CH];
    float base = 0.0f;
    float blank = 0.0f;
#pragma unroll
    for (int c = 0; c < CH; c++) {
        float x0 = __ldg(lp0 + c * TT + t);
        float x1 = __ldg(lp1 + c * TT + t);
        if (c == 0) blank = x1;
        float dd = x1 - x0;
        base += x0;
        d2[c] = pk2(dd, dd);
    }

    float* out = g_em + ((size_t)n * TT + t) * 256;
    out[0] = blank * LOG2E;

    const unsigned long long b2 = pk2(base, base);
    for (int j8 = 0; j8 < 32; j8++) {
        unsigned long long acc0 = b2, acc1 = b2, acc2 = b2, acc3 = b2;
#pragma unroll
        for (int c = 0; c < CH; c++) {
            const float4* mp = (const float4*)(maskf + c * 256 + j8 * 8);
            float4 f0 = mp[0];
            float4 f1 = mp[1];
            ffma2(acc0, pk2(f0.x, f0.y), d2[c]);
            ffma2(acc1, pk2(f0.z, f0.w), d2[c]);
            ffma2(acc2, pk2(f1.x, f1.y), d2[c]);
            ffma2(acc3, pk2(f1.z, f1.w), d2[c]);
        }
        float vx, vy;
        int j = j8 * 8;
        up2(acc0, vx, vy);
        if (j > 0) out[j] = vx * LOG2E;
        out[j + 1] = vy * LOG2E;
        up2(acc1, vx, vy);
        out[j + 2] = vx * LOG2E; out[j + 3] = vy * LOG2E;
        up2(acc2, vx, vy);
        out[j + 4] = vx * LOG2E; out[j + 5] = vy * LOG2E;
        up2(acc3, vx, vy);
        out[j + 6] = vx * LOG2E; out[j + 7] = vy * LOG2E;
    }
}

// =====================================================================
// Kernel 3: CTC forward — barrier-free wavefront, halo redundancy.
// 11 warps (352 thr). Warp w covers state-pairs [24w, 24w+32)
// (states [48w, 48w+64)), 8-pair halo overlap -> 8 steps between
// barriers. Alphas in registers; neighbor odd alpha via shfl.up.
// Emission rows staged per-block via cp.async, 2-block lookahead.
// =====================================================================
__device__ __forceinline__ void stage_rows(float (*sEm)[256], const float* emn,
                                           int r0, int tid) {
    if (tid < 256) {
#pragma unroll
        for (int q = 0; q < 2; q++) {
            int c = tid * 2 + q;
            int r = r0 + (c >> 6);
            int off = (c & 63) * 4;
            if (r < TT) {
                uint32_t dst = (uint32_t)__cvta_generic_to_shared(&sEm[r & 31][off]);
                const float* src = emn + (size_t)r * 256 + off;
                asm volatile("cp.async.cg.shared.global [%0], [%1], 16;\n"
                             :: "r"(dst), "l"(src));
            }
        }
    }
    asm volatile("cp.async.commit_group;\n" ::: "memory");
}

__global__ void __launch_bounds__(352) k_ctc() {
    const int n = blockIdx.x;
    const int tid = threadIdx.x;
    const int w = tid >> 5;
    const int l = tid & 31;
    const int kp = 24 * w + l;          // state-pair index (states 2kp, 2kp+1)

    __shared__ __align__(16) float sEm[32][256];   // emission row ring (32 KB)
    __shared__ __align__(8)  float2 A2[2][288];    // ping-pong alpha exchange

    const int tlen = g_tlen[n];
    const float* emn = g_em + (size_t)n * TT * 256;

    int labO = 0; bool skip = false;
    if (kp < tlen) {                    // tlen <= 255, labels in-bounds
        labO = g_labels[n * 256 + kp];
        if (kp >= 1) {
            int lm2 = g_labels[n * 256 + kp - 1];
            skip = (labO != 0) && (labO != lm2);
        }
    }

    // t=0 init into A2[0]
    for (int i = tid; i < 288; i += 352) {
        float2 v = make_float2(NEGF, NEGF);
        if (i == 0) {
            int lab0 = (tlen > 0) ? g_labels[n * 256] : 0;
            v = make_float2(__ldg(emn + 0), __ldg(emn + lab0));
        }
        A2[0][i] = v;
        A2[1][i] = make_float2(NEGF, NEGF);
    }

    stage_rows(sEm, emn, 1, tid);    // block 0 rows (t=1..8)
    stage_rows(sEm, emn, 9, tid);    // block 1 rows

    int buf = 0;
    int t = 1;
    for (int b = 0; b < 250; b++) {
        stage_rows(sEm, emn, 8 * b + 17, tid);          // block b+2 rows
        asm volatile("cp.async.wait_group 2;\n" ::: "memory");
        __syncthreads();              // A2 stores + staged rows visible

        float2 a = A2[buf][kp];
        float aE = a.x, aO = a.y;

#pragma unroll
        for (int s = 0; s < 8; s++) {
            if (t >= TT) break;
            const float* srow = &sEm[t & 31][0];
            float emE = srow[0];
            float emO = srow[labO];
            float aOprev = __shfl_up_sync(0xffffffffu, aO, 1);
            if (tid == 0) aOprev = NEGF;          // true left edge only

            // even state 2kp: lse(aE, aOprev)
            float mE = fmaxf(aE, aOprev);
            float dE = fminf(aE, aOprev) - mE;
            // odd state 2kp+1: lse(aO, aE, skip ? aOprev)
            float a2v = skip ? aOprev : NEGF;
            float hi = fmaxf(aO, aE), lo = fminf(aO, aE);
            float mO  = fmaxf(hi, a2v);
            float sec = fminf(hi, fmaxf(lo, a2v)) - mO;
            float th  = fminf(lo, a2v) - mO;

            float sE = 1.0f + ex2f(dE);
            float sO = 1.0f + ex2f(sec) + ex2f(th);
            aE = mE + lg2f(sE) + emE;
            aO = mO + lg2f(sO) + emO;
            t++;
        }

        // store valid lanes (warp 0 never shrinks; others valid for l>=8)
        if (w == 0 || l >= 8) A2[buf ^ 1][kp] = make_float2(aE, aO);
        buf ^= 1;
    }
    __syncthreads();

    if (tid == 0) {
        float ea = A2[buf][tlen].x;                       // alpha[2*tlen]
        float eb = A2[buf][(tlen >= 1) ? tlen - 1 : 0].y; // alpha[2*tlen-1]
        float m = fmaxf(ea, eb);
        float l2 = m + lg2f(ex2f(ea - m) + ex2f(eb - m));
        g_loss[n] = -l2 * LN2;
    }
}

// =====================================================================
// Kernel 4: deterministic mean
// =====================================================================
__global__ void k_reduce(float* __restrict__ out) {
    if (threadIdx.x == 0) {
        float s = 0.0f;
        for (int i = 0; i < NB; i++) s += g_loss[i];
        out[0] = s * (1.0f / (float)NB);
    }
}

// =====================================================================
extern "C" void kernel_launch(void* const* d_in, const int* in_sizes, int n_in,
                              void* d_out, int out_size) {
    const float* lp = (const float*)d_in[0];
    const int*   tg = (const int*)d_in[1];
    if (n_in >= 2 && in_sizes[0] == NB * CH * LL) {
        lp = (const float*)d_in[1];
        tg = (const int*)d_in[0];
    }

    k_preprocess<<<NB, 256>>>(tg);
    dim3 g2((TT + 127) / 128, NB);
    k_emission<<<g2, 128>>>(lp);
    k_ctc<<<NB, 352>>>();
    k_reduce<<<1, 32>>>((float*)d_out);
}

// round 5
// speedup vs baseline: 1.4207x; 1.0303x over previous
#include <cuda_runtime.h>
#include <cstdint>
#include <cstddef>

#define CH   40
#define TT   2000
#define LL   256
#define NB   64
#define NEGF (-1.0e30f)
#define LOG2E 1.4426950408889634f
#define LN2   0.6931471805599453f

// lg2(1+u) ~ poly(x), x = u-1, u in [0,2]  (Chebyshev of log2(2+x), deg 5)
#define D0 0.999835f
#define D1 0.721619f
#define D2 (-0.177414f)
#define D3 0.058070f
#define D4 (-0.029748f)
#define D5 0.0127536f

// ---------------- device scratch ----------------
__device__ unsigned long long g_maskkeys[NB * 256];
__device__ int   g_labels[NB * 256];
__device__ int   g_tlen[NB];
__device__ float g_em[(size_t)NB * TT * 256];   // emissions [n][t][j], log2-scaled
__device__ float g_loss[NB];
__device__ unsigned int g_done;

// ---------------- PTX helpers ----------------
__device__ __forceinline__ float ex2f(float x) {
    float r; asm("ex2.approx.ftz.f32 %0, %1;" : "=f"(r) : "f"(x)); return r;
}
__device__ __forceinline__ float lg2f(float x) {
    float r; asm("lg2.approx.ftz.f32 %0, %1;" : "=f"(r) : "f"(x)); return r;
}
__device__ __forceinline__ unsigned long long pk2(float x, float y) {
    unsigned long long r;
    asm("mov.b64 %0, {%1, %2};" : "=l"(r) : "f"(x), "f"(y));
    return r;
}
__device__ __forceinline__ void ffma2(unsigned long long &a, unsigned long long m, unsigned long long d) {
    asm("fma.rn.f32x2 %0, %1, %2, %3;" : "=l"(a) : "l"(m), "l"(d), "l"(a));
}
__device__ __forceinline__ void up2(unsigned long long v, float &x, float &y) {
    asm("mov.b64 {%0, %1}, %2;" : "=f"(x), "=f"(y) : "l"(v));
}

// =====================================================================
// Kernel 1: preprocessing (verified exact)
// =====================================================================
__global__ void k_preprocess(const int* __restrict__ targets) {
    const int n = blockIdx.x;
    const int l = threadIdx.x;

    __shared__ unsigned long long skey[256];
    __shared__ int sscan[256];
    __shared__ int sinv[256];

    if (n == 0 && l == 0) g_done = 0;   // reset fused-reduce ticket each launch

    unsigned long long key = 0ull;
#pragma unroll
    for (int c = 0; c < CH; c++) {
        key |= ((unsigned long long)(targets[(n * CH + c) * LL + l] & 1)) << (CH - 1 - c);
    }
    skey[l] = (key << 8) | (unsigned long long)l;
    __syncthreads();

    for (int k = 2; k <= 256; k <<= 1) {
        for (int j = k >> 1; j > 0; j >>= 1) {
            int ixj = l ^ j;
            if (ixj > l) {
                unsigned long long a = skey[l], b = skey[ixj];
                bool up = ((l & k) == 0);
                if ((a > b) == up) { skey[l] = b; skey[ixj] = a; }
            }
            __syncthreads();
        }
    }

    unsigned long long kv = skey[l] >> 8;
    unsigned long long kvp = (l > 0) ? (skey[l - 1] >> 8) : 0ull;
    int head = (l == 0 || kv != kvp) ? 1 : 0;
    sscan[l] = head;
    __syncthreads();
    for (int off = 1; off < 256; off <<= 1) {
        int v = sscan[l];
        int w = (l >= off) ? sscan[l - off] : 0;
        __syncthreads();
        sscan[l] = v + w;
        __syncthreads();
    }
    const int u   = sscan[255];
    const int uid = sscan[l] - 1;
    const int orig = (int)(skey[l] & 255ull);
    int inv2 = uid + 1; if (inv2 == u) inv2 = 0;
    sinv[orig] = inv2;
    if (head) g_maskkeys[n * 256 + inv2] = kv;
    __syncthreads();

    int flag = (l > 0 && sinv[l] != sinv[l - 1]) ? 1 : 0;
    int myinv = sinv[l];
    sscan[l] = flag;
    __syncthreads();
    for (int off = 1; off < 256; off <<= 1) {
        int v = sscan[l];
        int w = (l >= off) ? sscan[l - off] : 0;
        __syncthreads();
        sscan[l] = v + w;
        __syncthreads();
    }
    if (flag) g_labels[n * 256 + (sscan[l] - 1)] = myinv;
    if (l == 0) g_tlen[n] = sscan[255];
}

// =====================================================================
// Kernel 2: emission table (verified exact)
// =====================================================================
__global__ void __launch_bounds__(128) k_emission(const float* __restrict__ lp) {
    const int n = blockIdx.y;
    const int t = blockIdx.x * 128 + threadIdx.x;

    __shared__ float maskf[CH * 256];
    for (int idx = threadIdx.x; idx < CH * 256; idx += 128) {
        int c = idx >> 8, j = idx & 255;
        unsigned long long mk = g_maskkeys[n * 256 + j];
        maskf[idx] = (float)((mk >> (CH - 1 - c)) & 1ull);
    }
    __syncthreads();
    if (t >= TT) return;

    const float* lp0 = lp + ((size_t)n * 2 + 0) * CH * TT;
    const float* lp1 = lp + ((size_t)n * 2 + 1) * CH * TT;

    unsigned long long d2[CH];
    float base = 0.0f;
    float blank = 0.0f;
#pragma unroll
    for (int c = 0; c < CH; c++) {
        float x0 = __ldg(lp0 + c * TT + t);
        float x1 = __ldg(lp1 + c * TT + t);
        if (c == 0) blank = x1;
        float dd = x1 - x0;
        base += x0;
        d2[c] = pk2(dd, dd);
    }

    float* out = g_em + ((size_t)n * TT + t) * 256;
    out[0] = blank * LOG2E;

    const unsigned long long b2 = pk2(base, base);
    for (int j8 = 0; j8 < 32; j8++) {
        unsigned long long acc0 = b2, acc1 = b2, acc2 = b2, acc3 = b2;
#pragma unroll
        for (int c = 0; c < CH; c++) {
            const float4* mp = (const float4*)(maskf + c * 256 + j8 * 8);
            float4 f0 = mp[0];
            float4 f1 = mp[1];
            ffma2(acc0, pk2(f0.x, f0.y), d2[c]);
            ffma2(acc1, pk2(f0.z, f0.w), d2[c]);
            ffma2(acc2, pk2(f1.x, f1.y), d2[c]);
            ffma2(acc3, pk2(f1.z, f1.w), d2[c]);
        }
        float vx, vy;
        int j = j8 * 8;
        up2(acc0, vx, vy);
        if (j > 0) out[j] = vx * LOG2E;
        out[j + 1] = vy * LOG2E;
        up2(acc1, vx, vy);
        out[j + 2] = vx * LOG2E; out[j + 3] = vy * LOG2E;
        up2(acc2, vx, vy);
        out[j + 4] = vx * LOG2E; out[j + 5] = vy * LOG2E;
        up2(acc3, vx, vy);
        out[j + 6] = vx * LOG2E; out[j + 7] = vy * LOG2E;
    }
}

// =====================================================================
// Kernel 3: CTC forward — halo wavefront, poly-lg2 (MUFU 5->3 per pair),
// branch-free 8-step windows, fused final mean reduction.
// =====================================================================
__device__ __forceinline__ void stage_rows(float (*sEm)[256], const float* emn,
                                           int r0, int tid) {
    if (tid < 256) {
#pragma unroll
        for (int q = 0; q < 2; q++) {
            int c = tid * 2 + q;
            int r = r0 + (c >> 6);
            int off = (c & 63) * 4;
            if (r < TT) {
                uint32_t dst = (uint32_t)__cvta_generic_to_shared(&sEm[r & 31][off]);
                const float* src = emn + (size_t)r * 256 + off;
                asm volatile("cp.async.cg.shared.global [%0], [%1], 16;\n"
                             :: "r"(dst), "l"(src));
            }
        }
    }
    asm volatile("cp.async.commit_group;\n" ::: "memory");
}

__device__ __forceinline__ float lg2_poly(float u) {   // lg2(1+u), u in [0,2]
    float x = u - 1.0f;
    float p = fmaf(D5, x, D4);
    p = fmaf(p, x, D3);
    p = fmaf(p, x, D2);
    p = fmaf(p, x, D1);
    p = fmaf(p, x, D0);
    return p;
}

__global__ void __launch_bounds__(352) k_ctc(float* __restrict__ d_out) {
    const int n = blockIdx.x;
    const int tid = threadIdx.x;
    const int w = tid >> 5;
    const int l = tid & 31;
    const int kp = 24 * w + l;

    __shared__ __align__(16) float sEm[32][256];
    __shared__ __align__(8)  float2 A2[2][288];

    const int tlen = g_tlen[n];
    const float* emn = g_em + (size_t)n * TT * 256;

    int labO = 0; bool skip = false;
    if (kp < tlen) {
        labO = g_labels[n * 256 + kp];
        if (kp >= 1) {
            int lm2 = g_labels[n * 256 + kp - 1];
            skip = (labO != 0) && (labO != lm2);
        }
    }

    for (int i = tid; i < 288; i += 352) {
        float2 v = make_float2(NEGF, NEGF);
        if (i == 0) {
            int lab0 = (tlen > 0) ? g_labels[n * 256] : 0;
            v = make_float2(__ldg(emn + 0), __ldg(emn + lab0));
        }
        A2[0][i] = v;
        A2[1][i] = make_float2(NEGF, NEGF);
    }

    stage_rows(sEm, emn, 1, tid);
    stage_rows(sEm, emn, 9, tid);

    int buf = 0;

#define STEP_AT(tt)                                                         \
    do {                                                                    \
        const float* srow = &sEm[(tt) & 31][0];                             \
        float emE = srow[0];                                                \
        float emO = srow[labO];                                             \
        float aOprev = __shfl_up_sync(0xffffffffu, aO, 1);                  \
        if (tid == 0) aOprev = NEGF;                                        \
        float mE = fmaxf(aE, aOprev);                                       \
        float dE = fminf(aE, aOprev) - mE;                                  \
        float cc = skip ? aOprev : NEGF;                                    \
        float hi = fmaxf(aO, aE), lo = fminf(aO, aE);                       \
        float mO  = fmaxf(hi, cc);                                          \
        float sec = fminf(hi, fmaxf(lo, cc)) - mO;                          \
        float th  = fminf(lo, cc) - mO;                                     \
        float uE = ex2f(dE);                                                \
        float uO = ex2f(sec) + ex2f(th);                                    \
        aE = mE + lg2_poly(uE) + emE;                                       \
        aO = mO + lg2_poly(uO) + emO;                                       \
    } while (0)

    for (int b = 0; b < 249; b++) {
        stage_rows(sEm, emn, 8 * b + 17, tid);
        asm volatile("cp.async.wait_group 2;\n" ::: "memory");
        __syncthreads();

        float2 a = A2[buf][kp];
        float aE = a.x, aO = a.y;
        const int t0 = 8 * b + 1;
#pragma unroll
        for (int s = 0; s < 8; s++) STEP_AT(t0 + s);

        if (w == 0 || l >= 8) A2[buf ^ 1][kp] = make_float2(aE, aO);
        buf ^= 1;
    }

    // tail: t = 1993..1999 (7 steps)
    asm volatile("cp.async.wait_group 0;\n" ::: "memory");
    __syncthreads();
    {
        float2 a = A2[buf][kp];
        float aE = a.x, aO = a.y;
#pragma unroll
        for (int s = 0; s < 7; s++) STEP_AT(1993 + s);
        if (w == 0 || l >= 8) A2[buf ^ 1][kp] = make_float2(aE, aO);
        buf ^= 1;
    }
#undef STEP_AT
    __syncthreads();

    if (tid == 0) {
        float ea = A2[buf][tlen].x;
        float eb = A2[buf][(tlen >= 1) ? tlen - 1 : 0].y;
        float m = fmaxf(ea, eb);
        float l2 = m + lg2f(ex2f(ea - m) + ex2f(eb - m));
        g_loss[n] = -l2 * LN2;
        __threadfence();
        unsigned int tk = atomicAdd(&g_done, 1u);
        if (tk == NB - 1) {
            volatile float* gl = g_loss;
            float s = 0.0f;
            for (int i = 0; i < NB; i++) s += gl[i];
            d_out[0] = s * (1.0f / (float)NB);
        }
    }
}

// =====================================================================
extern "C" void kernel_launch(void* const* d_in, const int* in_sizes, int n_in,
                              void* d_out, int out_size) {
    const float* lp = (const float*)d_in[0];
    const int*   tg = (const int*)d_in[1];
    if (n_in >= 2 && in_sizes[0] == NB * CH * LL) {
        lp = (const float*)d_in[1];
        tg = (const int*)d_in[0];
    }

    k_preprocess<<<NB, 256>>>(tg);
    dim3 g2((TT + 127) / 128, NB);
    k_emission<<<g2, 128>>>(lp);
    k_ctc<<<NB, 352>>>((float*)d_out);
}